// round 8
// baseline (speedup 1.0000x reference)
#include <cuda_runtime.h>
#include <cuda_fp16.h>
#include <cfloat>
#include <stdint.h>

// x [64,256,32,32] f32, codebook [1024,256] f32
#define D_DIM   256
#define HW_DIM  1024
#define NPIX    65536
#define KCODE   1024
#define TOT_ELEMS 16777216
#define CAP     96

// Scratch (device globals; allocation-free)
__device__ float  g_cn[KCODE];
__device__ float  g_xn[NPIX];
__device__ float  g_l1x[NPIX];
__device__ float  g_xsn[NPIX * 4];     // per-pixel 64-dim segment L2 norms
__device__ int    g_csq_bits[4];       // global max per-segment ||c_seg||^2 (bits)
__device__ unsigned short g_cand[(size_t)NPIX * CAP];
__device__ unsigned char  g_cnt[NPIX];
__device__ int    g_idx[NPIX];
__device__ double g_partial[512];

// ---------------------------------------------------------------------------
// Codebook norms: exact cn (scalar-seq chain) + per-64-dim-segment max sumsq
// ---------------------------------------------------------------------------
__global__ void cnorm_kernel(const float* __restrict__ cb) {
    int k = blockIdx.x * 256 + threadIdx.x;
    const float* row = cb + (size_t)k * D_DIM;
    float s = 0.f;
    float seg[4] = {0.f, 0.f, 0.f, 0.f};
    for (int d = 0; d < D_DIM; d++) {
        float v = row[d];
        s = __fadd_rn(s, __fmul_rn(v, v));
        seg[d >> 6] += v * v;
    }
    g_cn[k] = s;
#pragma unroll
    for (int q = 0; q < 4; q++)
        atomicMax(&g_csq_bits[q], __float_as_int(seg[q] * 1.001f));
}

// ---------------------------------------------------------------------------
// Pixel norms: exact xn (d-ascending chain, bit-exact-validated), L1, seg norms
// ---------------------------------------------------------------------------
__global__ void xnorm_kernel(const float* __restrict__ x) {
    int b = blockIdx.x, t = threadIdx.x;
#pragma unroll
    for (int sblk = 0; sblk < 4; sblk++) {
        int hw = sblk * 256 + t;
        const float* xp = x + (size_t)b * D_DIM * HW_DIM + hw;
        float sa = 0.f, l1 = 0.f;
        float seg[4] = {0.f, 0.f, 0.f, 0.f};
        for (int d = 0; d < D_DIM; d++) {
            float v = xp[(size_t)d * HW_DIM];
            sa = __fadd_rn(sa, __fmul_rn(v, v));
            l1 += fabsf(v);
            seg[d >> 6] += v * v;
        }
        int p = b * HW_DIM + hw;
        g_xn[p]  = sa;
        g_l1x[p] = l1;
#pragma unroll
        for (int q = 0; q < 4; q++)
            g_xsn[p * 4 + q] = sqrtf(seg[q]) * 1.001f;
    }
}

// ---------------------------------------------------------------------------
// Filter: fp16 HFMA2 GEMM (64 px x 1024 codes x 256 d per CTA), half2 chains
// folded to f32 every 64 dims; provably-safe per-pixel threshold; candidates
// via smem atomics. Exact argmin (and its ties) provably in the candidate set.
// ---------------------------------------------------------------------------
__global__ __launch_bounds__(256, 2)
void filter_kernel(const float* __restrict__ x, const float* __restrict__ cb) {
    __shared__ __half2 As[16][64];      // [dk2][px]
    __shared__ __half2 Bs[16][132];     // [dk2][code] (+4 pad)
    __shared__ float cns[KCODE];
    __shared__ float bv[64], thrv[64];
    __shared__ int   cnts[64];
    __shared__ unsigned short cand[64 * CAP];   // 12KB

    const int t = threadIdx.x, lane = t & 31, wid = t >> 5;
    const int p0 = blockIdx.x * 64, bimg = p0 >> 10, hwb = p0 & 1023;
    const float* xb = x + (size_t)bimg * D_DIM * HW_DIM + hwb;

#pragma unroll
    for (int i = 0; i < 4; i++) cns[t + i * 256] = g_cn[t + i * 256];
    if (t < 64) {
        int p = p0 + t;
        float E = 0.f;
#pragma unroll
        for (int q = 0; q < 4; q++)
            E += g_xsn[p * 4 + q] * sqrtf(__int_as_float(g_csq_bits[q]));
        E = E * (0.03125f * 1.03f);            // 64 * 2^-11 per-seg fp16 accum
        E += g_l1x[p] * 1.2e-6f;               // input quantization
        thrv[t] = 4.f * E + 3e-4f;             // d2-window: 2 * (2E) + slack
        bv[t] = FLT_MAX;
        cnts[t] = 0;
    }

    // loader thread mapping
    const int am  = t >> 4, apx = (t & 15) * 4;   // A: dk2 row, 4 px
    const int bcode = t >> 1, bm0 = (t & 1) * 8;  // B: code, dk2 base (8 rows)

    // prefetch (nc=0, kc=0)
    float4 rae, rao, rb0, rb1, rb2, rb3;
    {
        rae = *(const float4*)(xb + (size_t)(2 * am) * HW_DIM + apx);
        rao = *(const float4*)(xb + (size_t)(2 * am + 1) * HW_DIM + apx);
        const float* bb = cb + (size_t)bcode * D_DIM + bm0 * 2;
        rb0 = *(const float4*)(bb);
        rb1 = *(const float4*)(bb + 4);
        rb2 = *(const float4*)(bb + 8);
        rb3 = *(const float4*)(bb + 12);
    }

    for (int nc = 0; nc < 8; nc++) {
        const int cbase = nc * 128;
        __half2 hacc[8][4];
        float   facc[8][4];
        const __half2 hz = __float2half2_rn(0.f);
#pragma unroll
        for (int i = 0; i < 8; i++)
#pragma unroll
            for (int j = 0; j < 4; j++) { hacc[i][j] = hz; facc[i][j] = 0.f; }

        for (int kc = 0; kc < 8; kc++) {
            __syncthreads();
            // STS A (4 half2 = 16B)
            {
                __half2 tmp[4];
                tmp[0] = __floats2half2_rn(rae.x, rao.x);
                tmp[1] = __floats2half2_rn(rae.y, rao.y);
                tmp[2] = __floats2half2_rn(rae.z, rao.z);
                tmp[3] = __floats2half2_rn(rae.w, rao.w);
                *(uint4*)&As[am][apx] = *(uint4*)tmp;
            }
            // STS B (8 half2)
            Bs[bm0 + 0][bcode] = __floats2half2_rn(rb0.x, rb0.y);
            Bs[bm0 + 1][bcode] = __floats2half2_rn(rb0.z, rb0.w);
            Bs[bm0 + 2][bcode] = __floats2half2_rn(rb1.x, rb1.y);
            Bs[bm0 + 3][bcode] = __floats2half2_rn(rb1.z, rb1.w);
            Bs[bm0 + 4][bcode] = __floats2half2_rn(rb2.x, rb2.y);
            Bs[bm0 + 5][bcode] = __floats2half2_rn(rb2.z, rb2.w);
            Bs[bm0 + 6][bcode] = __floats2half2_rn(rb3.x, rb3.y);
            Bs[bm0 + 7][bcode] = __floats2half2_rn(rb3.z, rb3.w);
            __syncthreads();

            // prefetch next chunk
            if (!(nc == 7 && kc == 7)) {
                const int nkc = (kc < 7) ? kc + 1 : 0;
                const int nnc = (kc < 7) ? nc : nc + 1;
                rae = *(const float4*)(xb + (size_t)(nkc * 32 + 2 * am) * HW_DIM + apx);
                rao = *(const float4*)(xb + (size_t)(nkc * 32 + 2 * am + 1) * HW_DIM + apx);
                const float* bb = cb + (size_t)(nnc * 128 + bcode) * D_DIM
                                     + nkc * 32 + bm0 * 2;
                rb0 = *(const float4*)(bb);
                rb1 = *(const float4*)(bb + 4);
                rb2 = *(const float4*)(bb + 8);
                rb3 = *(const float4*)(bb + 12);
            }

            // compute: 16 dk2 x (8 px x 4 codes) hfma2
#pragma unroll
            for (int m = 0; m < 16; m++) {
                uint4 ua0 = *(const uint4*)&As[m][wid * 8];       // broadcast
                uint4 ua1 = *(const uint4*)&As[m][wid * 8 + 4];
                uint4 ub  = *(const uint4*)&Bs[m][lane * 4];
                __half2 a[8], b[4];
                a[0] = *(__half2*)&ua0.x; a[1] = *(__half2*)&ua0.y;
                a[2] = *(__half2*)&ua0.z; a[3] = *(__half2*)&ua0.w;
                a[4] = *(__half2*)&ua1.x; a[5] = *(__half2*)&ua1.y;
                a[6] = *(__half2*)&ua1.z; a[7] = *(__half2*)&ua1.w;
                b[0] = *(__half2*)&ub.x;  b[1] = *(__half2*)&ub.y;
                b[2] = *(__half2*)&ub.z;  b[3] = *(__half2*)&ub.w;
#pragma unroll
                for (int i = 0; i < 8; i++)
#pragma unroll
                    for (int j = 0; j < 4; j++)
                        hacc[i][j] = __hfma2(a[i], b[j], hacc[i][j]);
            }

            if (kc & 1) {   // fold to f32 every 64 dims
#pragma unroll
                for (int i = 0; i < 8; i++)
#pragma unroll
                    for (int j = 0; j < 4; j++) {
                        facc[i][j] = __fadd_rn(facc[i][j],
                            __fadd_rn(__low2float(hacc[i][j]),
                                      __high2float(hacc[i][j])));
                        hacc[i][j] = hz;
                    }
            }
        }

        // epilogue stage 1: refine per-pixel running min
#pragma unroll
        for (int i = 0; i < 8; i++) {
            float m = FLT_MAX;
#pragma unroll
            for (int j = 0; j < 4; j++) {
                float s = __fadd_rn(cns[cbase + lane * 4 + j],
                                    -__fmul_rn(2.f, facc[i][j]));
                m = fminf(m, s);
            }
#pragma unroll
            for (int off = 16; off > 0; off >>= 1)
                m = fminf(m, __shfl_xor_sync(0xffffffffu, m, off));
            if (lane == 0) {
                int r = wid * 8 + i;
                bv[r] = fminf(bv[r], m);   // unique warp per pixel row
            }
        }
        __syncthreads();
        // stage 2: push candidates within provable threshold
#pragma unroll
        for (int i = 0; i < 8; i++) {
            const int r = wid * 8 + i;
            const float lim = bv[r] + thrv[r];
#pragma unroll
            for (int j = 0; j < 4; j++) {
                float s = __fadd_rn(cns[cbase + lane * 4 + j],
                                    -__fmul_rn(2.f, facc[i][j]));
                if (s <= lim) {
                    int slot = atomicAdd(&cnts[r], 1);
                    if (slot < CAP)
                        cand[r * CAP + slot] =
                            (unsigned short)(cbase + lane * 4 + j);
                }
            }
        }
    }
    __syncthreads();

    if (t < 64) {
        int p = p0 + t, c = cnts[t];
        if (c > CAP) g_cnt[p] = 255;
        else {
            g_cnt[p] = (unsigned char)c;
            for (int s = 0; s < c; s++)
                g_cand[(size_t)p * CAP + s] = cand[t * CAP + s];
        }
    }
}

// ---------------------------------------------------------------------------
// Rescore: exact fp32 chain (single accumulator, d ascending, fused FMA),
// reference rounding, lowest-index ties. Fallback = full scan.
// ---------------------------------------------------------------------------
__device__ __forceinline__ void eval_code(const float* __restrict__ xp,
                                          const float* __restrict__ cb,
                                          float xn, int k, float& bvv, int& bi) {
    const float* ck = cb + (size_t)k * D_DIM;
    float acc = 0.f;
#pragma unroll 8
    for (int d = 0; d < D_DIM; d++)
        acc = __fmaf_rn(xp[(size_t)d * HW_DIM], ck[d], acc);
    float v = __fadd_rn(__fadd_rn(xn, __fmul_rn(-2.f, acc)), g_cn[k]);
    if (v < bvv || (v == bvv && k < bi)) { bvv = v; bi = k; }
}

__global__ void rescore_kernel(const float* __restrict__ x,
                               const float* __restrict__ cb) {
    int p = blockIdx.x * 256 + threadIdx.x;
    int bimg = p >> 10, hw = p & 1023;
    const float* xp = x + (size_t)bimg * D_DIM * HW_DIM + hw;
    float xn = g_xn[p];
    int c = g_cnt[p];
    float bvv = FLT_MAX; int bi = 0x7fffffff;
    if (c == 255) {
        for (int k = 0; k < KCODE; k++) eval_code(xp, cb, xn, k, bvv, bi);
    } else {
        for (int i = 0; i < c; i++)
            eval_code(xp, cb, xn, g_cand[(size_t)p * CAP + i], bvv, bi);
    }
    g_idx[p] = bi;
}

// ---------------------------------------------------------------------------
// Output: gather + STE rounding + loss partial
// ---------------------------------------------------------------------------
__global__ __launch_bounds__(256)
void output_kernel(const float* __restrict__ x, const float* __restrict__ cb,
                   float* __restrict__ out) {
    __shared__ int besti[128];
    __shared__ double red[256];
    const int t = threadIdx.x;
    const int p0 = blockIdx.x * 128, bimg = p0 >> 10, hwb = p0 & 1023;
    if (t < 128) besti[t] = g_idx[p0 + t];
    __syncthreads();

    double lsum = 0.0;
#pragma unroll 4
    for (int m = 0; m < 32; m++) {
        int e4 = m * 256 + t;
        int d  = e4 >> 5;
        int pp = (e4 & 31) * 4;
        size_t addr = (size_t)(bimg * D_DIM + d) * HW_DIM + hwb + pp;
        float4 xv = *(const float4*)(x + addr);
        float q0 = cb[(size_t)besti[pp + 0] * D_DIM + d];
        float q1 = cb[(size_t)besti[pp + 1] * D_DIM + d];
        float q2 = cb[(size_t)besti[pp + 2] * D_DIM + d];
        float q3 = cb[(size_t)besti[pp + 3] * D_DIM + d];
        float4 o;
        o.x = __fadd_rn(xv.x, __fsub_rn(q0, xv.x));
        o.y = __fadd_rn(xv.y, __fsub_rn(q1, xv.y));
        o.z = __fadd_rn(xv.z, __fsub_rn(q2, xv.z));
        o.w = __fadd_rn(xv.w, __fsub_rn(q3, xv.w));
        *(float4*)(out + addr) = o;
        float d0 = __fsub_rn(xv.x, q0), d1 = __fsub_rn(xv.y, q1);
        float d2 = __fsub_rn(xv.z, q2), d3 = __fsub_rn(xv.w, q3);
        lsum += (double)__fmul_rn(d0, d0) + (double)__fmul_rn(d1, d1)
              + (double)__fmul_rn(d2, d2) + (double)__fmul_rn(d3, d3);
    }
    red[t] = lsum;
    __syncthreads();
    for (int s = 128; s > 0; s >>= 1) {
        if (t < s) red[t] += red[t + s];
        __syncthreads();
    }
    if (t == 0) g_partial[blockIdx.x] = red[0];
}

__global__ void finalize_kernel(float* __restrict__ out, int out_size) {
    __shared__ double red[512];
    int t = threadIdx.x;
    red[t] = g_partial[t];
    __syncthreads();
    for (int s = 256; s > 0; s >>= 1) {
        if (t < s) red[t] += red[t + s];
        __syncthreads();
    }
    if (t == 0) {
        float loss = (float)(1.25 * red[0] / (double)TOT_ELEMS);
        for (int i = TOT_ELEMS; i < out_size; i++) out[i] = loss;
    }
}

// ---------------------------------------------------------------------------
extern "C" void kernel_launch(void* const* d_in, const int* in_sizes, int n_in,
                              void* d_out, int out_size) {
    const float* x  = (const float*)d_in[0];
    const float* cb = (const float*)d_in[1];
    float* out = (float*)d_out;

    cnorm_kernel<<<KCODE / 256, 256>>>(cb);
    xnorm_kernel<<<64, 256>>>(x);
    filter_kernel<<<NPIX / 64, 256>>>(x, cb);
    rescore_kernel<<<NPIX / 256, 256>>>(x, cb);
    output_kernel<<<NPIX / 128, 256>>>(x, cb, out);
    finalize_kernel<<<1, 512>>>(out, out_size);
}

// round 9
// speedup vs baseline: 17.0489x; 17.0489x over previous
#include <cuda_runtime.h>
#include <cfloat>
#include <stdint.h>

// x [64,256,32,32] f32, codebook [1024,256] f32
#define D_DIM   256
#define HW_DIM  1024
#define NPIX    65536
#define KCODE   1024
#define TOT_ELEMS 16777216

typedef unsigned long long u64;

// Scratch (device globals; allocation-free)
__device__ float  g_cn[KCODE];
__device__ float  g_xn[NPIX];
__device__ double g_partial[512];

// ===================== packed f32x2 helpers (sm_100+) =====================
__device__ __forceinline__ u64 fma2(u64 a, u64 b, u64 c) {
    u64 d;
    asm("fma.rn.f32x2 %0, %1, %2, %3;" : "=l"(d) : "l"(a), "l"(b), "l"(c));
    return d;
}
__device__ __forceinline__ u64 dup2(float v) {
    u64 d;
    asm("mov.b64 %0, {%1, %1};" : "=l"(d) : "f"(v));
    return d;
}
__device__ __forceinline__ float lo2(u64 v) {
    float l, h;
    asm("mov.b64 {%0, %1}, %2;" : "=f"(l), "=f"(h) : "l"(v));
    return l;
}
__device__ __forceinline__ float hi2(u64 v) {
    float l, h;
    asm("mov.b64 {%0, %1}, %2;" : "=f"(l), "=f"(h) : "l"(v));
    return h;
}

// B smem column swizzle: codes at word c + 4*(c>>5); 8-lane LDS.128 phases
// then cover all 32 banks (conflict-free). Row pitch 140 words (560B, 16B mult).
#define BPITCH 140
__device__ __forceinline__ int bcol(int c) { return c + 4 * (c >> 5); }

// ---------------------------------------------------------------------------
// norms (scalar-sequential order — bit-exact-validated in round 2)
// ---------------------------------------------------------------------------
__global__ void cnorm_kernel(const float* __restrict__ cb) {
    int k = blockIdx.x * 256 + threadIdx.x;
    const float* row = cb + (size_t)k * D_DIM;
    float s = 0.f;
    for (int d = 0; d < D_DIM; d++) s = __fadd_rn(s, __fmul_rn(row[d], row[d]));
    g_cn[k] = s;
}
__global__ void xnorm_kernel(const float* __restrict__ x) {
    int b = blockIdx.x, t = threadIdx.x;
    const float* xb = x + (size_t)b * D_DIM * HW_DIM + t * 4;
    float sa[4] = {0.f, 0.f, 0.f, 0.f};
    for (int d = 0; d < D_DIM; d++) {
        float4 v = *(const float4*)(xb + (size_t)d * HW_DIM);
        sa[0] = __fadd_rn(sa[0], __fmul_rn(v.x, v.x));
        sa[1] = __fadd_rn(sa[1], __fmul_rn(v.y, v.y));
        sa[2] = __fadd_rn(sa[2], __fmul_rn(v.z, v.z));
        sa[3] = __fadd_rn(sa[3], __fmul_rn(v.w, v.w));
    }
    int p = b * HW_DIM + t * 4;
#pragma unroll
    for (int j = 0; j < 4; j++) g_xn[p + j] = sa[j];
}

// ---------------------------------------------------------------------------
// Main VQ: 128x1024x256 fp32 GEMM via fma.rn.f32x2, duplicate-pixel x natural
// code-pair form. Each 32-bit lane is an exact single-accumulator d-ascending
// fused-FMA chain (bit-identical to the validated round-2 kernel).
// ---------------------------------------------------------------------------
__global__ __launch_bounds__(256, 2)
void vq_kernel(const float* __restrict__ x,
               const float* __restrict__ cb,
               float* __restrict__ out) {
    __shared__ __align__(16) float As[16][128];     // [dk][pixel]
    __shared__ __align__(16) float Bs[16][BPITCH];  // [dk][swizzled code]
    __shared__ float cns[KCODE];
    __shared__ float xns[128];
    __shared__ float bestv[128];
    __shared__ int   besti[128];
    __shared__ double red[256];

    const int t  = threadIdx.x;
    const int tx = t & 15;
    const int ty = t >> 4;
    const int p0   = blockIdx.x * 128;
    const int bimg = p0 >> 10;
    const int hwb  = p0 & 1023;
    const float* xb = x + (size_t)bimg * D_DIM * HW_DIM + hwb;

#pragma unroll
    for (int i = 0; i < 4; i++) cns[t + i * 256] = g_cn[t + i * 256];
    if (t < 128) {
        xns[t] = g_xn[p0 + t];
        bestv[t] = FLT_MAX; besti[t] = 0x7fffffff;
    }
    __syncthreads();

    // loader mappings (as round 2)
    const int dkA0 = t >> 5;
    const int dkA1 = dkA0 + 8;
    const int ppA  = (t & 31) * 4;
    const int cc0  = t >> 2;
    const int cc1  = cc0 + 64;
    const int ds0  = (t & 3) * 4;
    const int col0 = bcol(cc0);
    const int col1 = bcol(cc1);
    // reader column base: codes tx*8..tx*8+7 are contiguous after swizzle
    const int rcol = tx * 8 + 4 * (tx >> 2);

    for (int nc = 0; nc < 8; nc++) {
        const int cbase = nc * 128;

        // acc2[i][jp]: {dot(px_i, c_{2jp}), dot(px_i, c_{2jp+1})}
        u64 acc2[8][4];
#pragma unroll
        for (int i = 0; i < 8; i++)
#pragma unroll
            for (int j = 0; j < 4; j++) acc2[i][j] = 0ull;

        float4 ra0, ra1, rb0, rb1;
        {
            ra0 = *(const float4*)(xb + (size_t)dkA0 * HW_DIM + ppA);
            ra1 = *(const float4*)(xb + (size_t)dkA1 * HW_DIM + ppA);
            rb0 = *(const float4*)(cb + (size_t)(cbase + cc0) * D_DIM + ds0);
            rb1 = *(const float4*)(cb + (size_t)(cbase + cc1) * D_DIM + ds0);
        }

        for (int kc = 0; kc < 16; kc++) {
            __syncthreads();
            *(float4*)&As[dkA0][ppA] = ra0;
            *(float4*)&As[dkA1][ppA] = ra1;
            Bs[ds0 + 0][col0] = rb0.x; Bs[ds0 + 1][col0] = rb0.y;
            Bs[ds0 + 2][col0] = rb0.z; Bs[ds0 + 3][col0] = rb0.w;
            Bs[ds0 + 0][col1] = rb1.x; Bs[ds0 + 1][col1] = rb1.y;
            Bs[ds0 + 2][col1] = rb1.z; Bs[ds0 + 3][col1] = rb1.w;
            __syncthreads();

            if (kc < 15) {
                const int kn = kc + 1;
                ra0 = *(const float4*)(xb + (size_t)(kn * 16 + dkA0) * HW_DIM + ppA);
                ra1 = *(const float4*)(xb + (size_t)(kn * 16 + dkA1) * HW_DIM + ppA);
                rb0 = *(const float4*)(cb + (size_t)(cbase + cc0) * D_DIM + kn * 16 + ds0);
                rb1 = *(const float4*)(cb + (size_t)(cbase + cc1) * D_DIM + kn * 16 + ds0);
            }

#pragma unroll
            for (int dk = 0; dk < 16; dk++) {
                float4 af0 = *(const float4*)&As[dk][ty * 8];       // broadcast
                float4 af1 = *(const float4*)&As[dk][ty * 8 + 4];
                ulonglong2 bq0 = *(const ulonglong2*)&Bs[dk][rcol];     // pairs 0,1
                ulonglong2 bq1 = *(const ulonglong2*)&Bs[dk][rcol + 4]; // pairs 2,3
                u64 bp[4] = {bq0.x, bq0.y, bq1.x, bq1.y};
                float av[8] = {af0.x, af0.y, af0.z, af0.w,
                               af1.x, af1.y, af1.z, af1.w};
#pragma unroll
                for (int i = 0; i < 8; i++) {
                    u64 ad = dup2(av[i]);
#pragma unroll
                    for (int jp = 0; jp < 4; jp++)
                        acc2[i][jp] = fma2(ad, bp[jp], acc2[i][jp]);
                }
            }
        }

        // Epilogue: d2 = fl(fl(xn - 2*dot) + cn); lowest-index ties on rounded
        // values, ascending code order; shfl-reduce across the 16-lane tx group.
#pragma unroll
        for (int i = 0; i < 8; i++) {
            const int r = ty * 8 + i;
            const float xn = xns[r];
            float bv = FLT_MAX;
            int   bi = 0x7fffffff;
#pragma unroll
            for (int jp = 0; jp < 4; jp++) {
                const int c0 = cbase + tx * 8 + 2 * jp;
                float vlo = lo2(acc2[i][jp]);
                float vhi = hi2(acc2[i][jp]);
                float d0 = __fadd_rn(__fadd_rn(xn, __fmul_rn(-2.f, vlo)), cns[c0]);
                float d1 = __fadd_rn(__fadd_rn(xn, __fmul_rn(-2.f, vhi)), cns[c0 + 1]);
                if (d0 < bv) { bv = d0; bi = c0; }
                if (d1 < bv) { bv = d1; bi = c0 + 1; }
            }
#pragma unroll
            for (int off = 8; off > 0; off >>= 1) {
                float ov = __shfl_down_sync(0xffffffffu, bv, off, 16);
                int   oi = __shfl_down_sync(0xffffffffu, bi, off, 16);
                if (ov < bv || (ov == bv && oi < bi)) { bv = ov; bi = oi; }
            }
            if (tx == 0) {
                if (bv < bestv[r] || (bv == bestv[r] && bi < besti[r])) {
                    bestv[r] = bv; besti[r] = bi;
                }
            }
        }
    }
    __syncthreads();

    // Output: STE rounding fl(x + fl(q-x)); loss from fl(x-q)^2 in double.
    double lsum = 0.0;
#pragma unroll 4
    for (int m = 0; m < 128; m++) {
        int e  = m * 256 + t;
        int d  = e >> 7;
        int pp = e & 127;
        size_t addr = (size_t)(bimg * D_DIM + d) * HW_DIM + hwb + pp;
        float q  = cb[(size_t)besti[pp] * D_DIM + d];
        float xv = x[addr];
        out[addr] = __fadd_rn(xv, __fsub_rn(q, xv));
        float diff = __fsub_rn(xv, q);
        lsum += (double)__fmul_rn(diff, diff);
    }
    red[t] = lsum;
    __syncthreads();
    for (int s = 128; s > 0; s >>= 1) {
        if (t < s) red[t] += red[t + s];
        __syncthreads();
    }
    if (t == 0) g_partial[blockIdx.x] = red[0];
}

// ---------------------------------------------------------------------------
__global__ void finalize_kernel(float* __restrict__ out, int out_size) {
    __shared__ double red[512];
    int t = threadIdx.x;
    red[t] = g_partial[t];
    __syncthreads();
    for (int s = 256; s > 0; s >>= 1) {
        if (t < s) red[t] += red[t + s];
        __syncthreads();
    }
    if (t == 0) {
        float m = (float)(red[0] / (double)TOT_ELEMS);
        float loss = (float)(1.25 * (double)m);
        for (int i = TOT_ELEMS; i < out_size; i++) out[i] = loss;
    }
}

// ---------------------------------------------------------------------------
extern "C" void kernel_launch(void* const* d_in, const int* in_sizes, int n_in,
                              void* d_out, int out_size) {
    const float* x  = (const float*)d_in[0];
    const float* cb = (const float*)d_in[1];
    float* out = (float*)d_out;

    cnorm_kernel<<<KCODE / 256, 256>>>(cb);
    xnorm_kernel<<<64, 256>>>(x);
    vq_kernel<<<NPIX / 128, 256>>>(x, cb, out);
    finalize_kernel<<<1, 512>>>(out, out_size);
}